// round 4
// baseline (speedup 1.0000x reference)
#include <cuda_runtime.h>

#define RES         96
#define EPSF        1e-5f
#define CAP         (RES * RES)        // 9216 entries
#define MAIN_BLOCKS 148
#define NWG         (MAIN_BLOCKS * 32) // 4736 warps in main kernel

// Global scratch (no cudaMalloc allowed).
__device__ int   g_ptile[NWG * 2];          // tile id per (warp, record)
__device__ float g_part [NWG * 2 * 64];     // 64 partial sums per record
__device__ int   g_K;                       // compacted source count

// ---- f32x2 helpers ----------------------------------------------------------
__device__ __forceinline__ unsigned long long pk2(float a, float b) {
    unsigned long long r;
    asm("mov.b64 %0, {%1, %2};" : "=l"(r) : "f"(a), "f"(b));
    return r;
}
__device__ __forceinline__ void unpk2(unsigned long long v, float& a, float& b) {
    asm("mov.b64 {%0, %1}, %2;" : "=f"(a), "=f"(b) : "l"(v));
}

// ---- compile-time-deterministic tile geometry --------------------------------
// For each i-pair p (rows 2p, 2p+1): dmin = min row-distance to center;
// interior half-width wI = floor(sqrt(2208 - dmin^2)); windows of 32 columns
// starting at J0 = 47 - wI, nw = ceil((2wI+2)/32) of them. Identical code runs
// in both kernels -> identical tables.
__device__ __forceinline__ void build_tiles(int tid, int* tnw, int* tJ0,
                                             int* toff, int* ttab, int* pWT)
{
    if (tid < 48) {
        int p = tid;
        int d0 = 2 * p - 48;     if (d0 < 0) d0 = -d0;
        int d1 = 2 * p + 1 - 48; if (d1 < 0) d1 = -d1;
        int dmin = d0 < d1 ? d0 : d1;
        int v = 2208 - dmin * dmin;
        int nw = 0, J0 = 0;
        if (v >= 0) {
            int wI = (int)sqrtf((float)v);
            while ((wI + 1) * (wI + 1) <= v) wI++;   // exact isqrt
            while (wI * wI > v) wI--;
            J0 = 47 - wI;                            // >= 1 always
            nw = (2 * wI + 2 + 31) >> 5;             // <= 3
        }
        tnw[p] = nw; tJ0[p] = J0;
    }
    __syncthreads();
    if (tid == 0) {
        int s = 0;
        #pragma unroll 1
        for (int p = 0; p < 48; p++) { toff[p] = s; s += tnw[p]; }
        *pWT = s;                                    // WT <= 144
    }
    __syncthreads();
    if (tid < 48) {
        int p = tid;
        for (int g = 0; g < tnw[p]; g++)
            ttab[toff[p] + g] = p | (g << 8) | (tJ0[p] << 16);
    }
    __syncthreads();
}

// ==============================================================================
// Main kernel: compaction + flat, perfectly balanced potential evaluation.
// Grid 148 x 1024. Each warp takes a contiguous span of L = ceil(WT*K/4736)
// items from the flattened (tile, source) space (a span crosses <= 1 tile
// boundary since L << K), accumulates 2x32 target partials per tile fragment,
// and writes them to fixed global record slots (deterministic).
// ==============================================================================
__global__ void __launch_bounds__(1024, 1) main_kernel(
    const float* __restrict__ b, float* __restrict__ out)
{
    extern __shared__ float4 ent[];              // CAP * 16 B dynamic
    __shared__ int cnts[RES], offs[RES], sK;
    __shared__ int tnw[48], tJ0[48], toff[48], ttab[144], sWT;

    const int tid  = threadIdx.x;
    const int wid  = tid >> 5;
    const int lane = tid & 31;

    build_tiles(tid, tnw, tJ0, toff, ttab, &sWT);

    // ---- compaction: positive boundary -> (-bi, -bi, bj, w), row-major order
    {
        const int r0 = wid * 3;
        #pragma unroll
        for (int rr = 0; rr < 3; rr++) {
            const int row = r0 + rr;
            int c = 0;
            #pragma unroll
            for (int s = 0; s < 3; s++) {
                float v = b[row * RES + s * 32 + lane];
                c += __popc(__ballot_sync(0xffffffffu, v > 0.0f));
            }
            if (lane == 0) cnts[row] = c;
        }
    }
    __syncthreads();
    if (wid == 0) {                              // exclusive prefix of 96 counts
        int a0 = cnts[lane], a1 = cnts[lane + 32], a2 = cnts[lane + 64];
        int s0 = a0, s1 = a1, s2 = a2;
        #pragma unroll
        for (int d = 1; d < 32; d <<= 1) {
            int t0 = __shfl_up_sync(0xffffffffu, s0, d); if (lane >= d) s0 += t0;
            int t1 = __shfl_up_sync(0xffffffffu, s1, d); if (lane >= d) s1 += t1;
            int t2 = __shfl_up_sync(0xffffffffu, s2, d); if (lane >= d) s2 += t2;
        }
        s1 += __shfl_sync(0xffffffffu, s0, 31);
        s2 += __shfl_sync(0xffffffffu, s1, 31);
        offs[lane]      = s0 - a0;
        offs[lane + 32] = s1 - a1;
        offs[lane + 64] = s2 - a2;
        if (lane == 31) sK = s2;
    }
    __syncthreads();
    {
        const int r0 = wid * 3;
        #pragma unroll
        for (int rr = 0; rr < 3; rr++) {
            const int row = r0 + rr;
            int p = offs[row];
            #pragma unroll
            for (int s = 0; s < 3; s++) {
                const int col = s * 32 + lane;
                float v = b[row * RES + col];
                unsigned m = __ballot_sync(0xffffffffu, v > 0.0f);
                if (v > 0.0f) {
                    int pos = p + __popc(m & ((1u << lane) - 1u));
                    ent[pos] = make_float4(-(float)row, -(float)row, (float)col, v);
                }
                p += __popc(m);
            }
        }
    }
    __syncthreads();

    if (blockIdx.x == 0 && tid == 0) g_K = sK;   // persist K for finish kernel

    // ---- rim passthrough for all uncovered targets (blocks 0..47)
    if (blockIdx.x < 48 && tid < RES) {
        const int p = blockIdx.x, j = tid;
        const int nw = tnw[p], J0 = tJ0[p];
        const bool covered = (nw > 0) && (j >= J0) && (j < J0 + 32 * nw);
        if (!covered) {
            out[(2 * p) * RES + j]     = b[(2 * p) * RES + j];
            out[(2 * p + 1) * RES + j] = b[(2 * p + 1) * RES + j];
        }
    }

    // ---- flat balanced main loop
    const int K  = sK;
    const int WT = sWT;
    const int total = WT * K;
    const int L  = (total + NWG - 1) / NWG;
    const int wg = blockIdx.x * 32 + wid;
    int q0 = wg * L;
    int q1 = q0 + L; if (q1 > total) q1 = total;
    int rec = 0;

    while (q0 < q1) {
        const int t  = q0 / K;
        const int sa = q0 - t * K;
        int sb = sa + (q1 - q0); if (sb > K) sb = K;

        const int info = ttab[t];
        const int p  = info & 255;
        const int g  = (info >> 8) & 255;
        const int J0 = info >> 16;

        const float fi0 = (float)(2 * p);
        const float fj  = (float)(J0 + 32 * g + lane);   // may be >= 96 (discarded)
        const unsigned long long fi01 = pk2(fi0, fi0 + 1.0f);

        const float dic0 = fi0 - 48.0f;
        const float dic1 = dic0 + 1.0f;
        const float djc  = fj - 48.0f;
        const float z0 = 48.0f - sqrtf(dic0 * dic0 + djc * djc) + EPSF;
        const float z1 = 48.0f - sqrtf(dic1 * dic1 + djc * djc) + EPSF;
        const float c00 = fmaf(z0, z0, EPSF * EPSF);
        const float c01 = fmaf(z1, z1, EPSF * EPSF);

        float acc0 = 0.0f, acc1 = 0.0f;
        #pragma unroll 4
        for (int s = sa; s < sb; s++) {
            float4 e = ent[s];                           // broadcast LDS.128
            unsigned long long bi01 = pk2(e.x, e.y);
            unsigned long long di01;
            asm("add.rn.f32x2 %0, %1, %2;" : "=l"(di01) : "l"(fi01), "l"(bi01));
            float dj = fj - e.z;
            float u  = fmaf(dj, dj, c00);
            float v  = fmaf(dj, dj, c01);
            unsigned long long uv = pk2(u, v);
            unsigned long long den01;
            asm("fma.rn.f32x2 %0, %1, %2, %3;" : "=l"(den01)
                : "l"(di01), "l"(di01), "l"(uv));
            float den0, den1; unpk2(den01, den0, den1);
            float inv0, inv1;
            asm("rcp.approx.ftz.f32 %0, %1;" : "=f"(inv0) : "f"(den0));
            asm("rcp.approx.ftz.f32 %0, %1;" : "=f"(inv1) : "f"(den1));
            acc0 = fmaf(e.w, inv0, acc0);
            acc1 = fmaf(e.w, inv1, acc1);
        }

        const int slot = wg * 2 + rec;
        g_ptile[slot] = t;
        g_part[slot * 64 + lane]      = acc0;
        g_part[slot * 64 + 32 + lane] = acc1;
        rec++;
        q0 += sb - sa;
    }
    for (; rec < 2; rec++)
        if (lane == 0) g_ptile[wg * 2 + rec] = -1;
}

// ==============================================================================
// Finish kernel: block t combines partials of tile t in fixed (ascending warp)
// order and writes the 64 outputs with the exact integer rim select.
// Contributor range and record index are closed-form — no flags needed.
// ==============================================================================
__global__ void __launch_bounds__(64) finish_kernel(
    const float* __restrict__ b, float* __restrict__ out)
{
    __shared__ int tnw[48], tJ0[48], toff[48], ttab[144], sWT;
    const int tid = threadIdx.x;

    build_tiles(tid, tnw, tJ0, toff, ttab, &sWT);

    const int t = blockIdx.x;
    const int WT = sWT;
    if (t >= WT) return;

    const int info = ttab[t];
    const int p  = info & 255;
    const int g  = (info >> 8) & 255;
    const int J0 = info >> 16;

    const int K = g_K;
    const int total = WT * K;
    float s = 0.0f;
    if (total > 0) {
        const int L   = (total + NWG - 1) / NWG;
        const int wlo = (t * K) / L;
        const int whi = ((t + 1) * K - 1) / L;           // <= last working warp
        #pragma unroll 2
        for (int wg = wlo; wg <= whi; wg++) {
            const int r = t - (wg * L) / K;              // 0 or 1
            s += g_part[(wg * 2 + r) * 64 + tid];
        }
    }

    const int k  = tid >> 5;
    const int l  = tid & 31;
    const int ii = 2 * p + k;
    const int jj = J0 + 32 * g + l;
    if (jj < RES) {
        const int di = ii - 48, dj = jj - 48;
        const float bv = b[ii * RES + jj];
        out[ii * RES + jj] = (di * di + dj * dj >= 2209) ? bv : s;
    }
}

// ------------------------------------------------------------------------------
extern "C" void kernel_launch(void* const* d_in, const int* in_sizes, int n_in,
                              void* d_out, int out_size) {
    (void)in_sizes; (void)n_in; (void)out_size;
    const float* b   = (const float*)d_in[0];
    float*       out = (float*)d_out;

    const int smem_bytes = CAP * (int)sizeof(float4);    // 147456
    cudaFuncSetAttribute(main_kernel,
                         cudaFuncAttributeMaxDynamicSharedMemorySize, smem_bytes);

    main_kernel<<<MAIN_BLOCKS, 1024, smem_bytes>>>(b, out);
    finish_kernel<<<144, 64>>>(b, out);
}

// round 5
// speedup vs baseline: 1.1992x; 1.1992x over previous
#include <cuda_runtime.h>

#define RES         96
#define EPSF        1e-5f
#define CAP         (RES * RES)        // 9216 entries
#define MAIN_BLOCKS 148
#define NWG         (MAIN_BLOCKS * 32) // 4736 warps in main kernel
#define MAXFRAG     34                 // worst-case tile fragments per block

// Global scratch (static allocation — no cudaMalloc).
__device__ float g_frag[MAIN_BLOCKS * MAXFRAG * 64];  // block-level tile fragments
__device__ int   g_K;                                 // compacted source count

// ---- f32x2 helpers ----------------------------------------------------------
__device__ __forceinline__ unsigned long long pk2(float a, float b) {
    unsigned long long r;
    asm("mov.b64 %0, {%1, %2};" : "=l"(r) : "f"(a), "f"(b));
    return r;
}
__device__ __forceinline__ void unpk2(unsigned long long v, float& a, float& b) {
    asm("mov.b64 {%0, %1}, %2;" : "=f"(a), "=f"(b) : "l"(v));
}

// ---- deterministic tile geometry (identical in both kernels) -----------------
// i-pair p (rows 2p,2p+1): dmin = min row distance to center; interior
// half-width wI = floor(sqrt(2208 - dmin^2)); nw 32-wide windows from J0=47-wI.
__device__ __forceinline__ void build_tiles(int tid, int* tnw, int* tJ0,
                                             int* toff, int* ttab, int* pWT)
{
    if (tid < 48) {
        int p = tid;
        int d0 = 2 * p - 48;     if (d0 < 0) d0 = -d0;
        int d1 = 2 * p + 1 - 48; if (d1 < 0) d1 = -d1;
        int dmin = d0 < d1 ? d0 : d1;
        int v = 2208 - dmin * dmin;
        int nw = 0, J0 = 0;
        if (v >= 0) {
            int wI = (int)sqrtf((float)v);
            while ((wI + 1) * (wI + 1) <= v) wI++;   // exact isqrt
            while (wI * wI > v) wI--;
            J0 = 47 - wI;
            nw = (2 * wI + 2 + 31) >> 5;             // <= 3
        }
        tnw[p] = nw; tJ0[p] = J0;
    }
    __syncthreads();
    if (tid == 0) {
        int s = 0;
        #pragma unroll 1
        for (int p = 0; p < 48; p++) { toff[p] = s; s += tnw[p]; }
        *pWT = s;                                    // WT <= 144 (typ. 117)
    }
    __syncthreads();
    if (tid < 48) {
        int p = tid;
        for (int g = 0; g < tnw[p]; g++)
            ttab[toff[p] + g] = p | (g << 8) | (tJ0[p] << 16);
    }
    __syncthreads();
}

// ==============================================================================
// Main kernel: compaction + flat balanced evaluation + intra-block reduction.
// ==============================================================================
__global__ void __launch_bounds__(1024, 1) main_kernel(
    const float* __restrict__ b, float* __restrict__ out)
{
    extern __shared__ float4 ent[];              // CAP * 16 B dynamic
    __shared__ int   cnts[RES], offs[RES], sK;
    __shared__ int   tnw[48], tJ0[48], toff[48], ttab[144], sWT;
    __shared__ float spart[64 * 64];             // 32 warps x 2 records x 64
    __shared__ int   stile[64];
    __shared__ float red2[1024];

    const int tid  = threadIdx.x;
    const int wid  = tid >> 5;
    const int lane = tid & 31;

    build_tiles(tid, tnw, tJ0, toff, ttab, &sWT);

    // ---- compaction: positive boundary -> (-bi, -bi, bj, w), row-major order
    {
        const int r0 = wid * 3;
        #pragma unroll
        for (int rr = 0; rr < 3; rr++) {
            const int row = r0 + rr;
            int c = 0;
            #pragma unroll
            for (int s = 0; s < 3; s++) {
                float v = b[row * RES + s * 32 + lane];
                c += __popc(__ballot_sync(0xffffffffu, v > 0.0f));
            }
            if (lane == 0) cnts[row] = c;
        }
    }
    __syncthreads();
    if (wid == 0) {                              // exclusive prefix of 96 counts
        int a0 = cnts[lane], a1 = cnts[lane + 32], a2 = cnts[lane + 64];
        int s0 = a0, s1 = a1, s2 = a2;
        #pragma unroll
        for (int d = 1; d < 32; d <<= 1) {
            int t0 = __shfl_up_sync(0xffffffffu, s0, d); if (lane >= d) s0 += t0;
            int t1 = __shfl_up_sync(0xffffffffu, s1, d); if (lane >= d) s1 += t1;
            int t2 = __shfl_up_sync(0xffffffffu, s2, d); if (lane >= d) s2 += t2;
        }
        s1 += __shfl_sync(0xffffffffu, s0, 31);
        s2 += __shfl_sync(0xffffffffu, s1, 31);
        offs[lane]      = s0 - a0;
        offs[lane + 32] = s1 - a1;
        offs[lane + 64] = s2 - a2;
        if (lane == 31) sK = s2;
    }
    __syncthreads();
    {
        const int r0 = wid * 3;
        #pragma unroll
        for (int rr = 0; rr < 3; rr++) {
            const int row = r0 + rr;
            int p = offs[row];
            #pragma unroll
            for (int s = 0; s < 3; s++) {
                const int col = s * 32 + lane;
                float v = b[row * RES + col];
                unsigned m = __ballot_sync(0xffffffffu, v > 0.0f);
                if (v > 0.0f) {
                    int pos = p + __popc(m & ((1u << lane) - 1u));
                    ent[pos] = make_float4(-(float)row, -(float)row, (float)col, v);
                }
                p += __popc(m);
            }
        }
    }
    __syncthreads();

    if (blockIdx.x == 0 && tid == 0) g_K = sK;

    // ---- rim passthrough for uncovered columns (blocks 0..47)
    if (blockIdx.x < 48 && tid < RES) {
        const int p = blockIdx.x, j = tid;
        const int nw = tnw[p], J0 = tJ0[p];
        const bool covered = (nw > 0) && (j >= J0) && (j < J0 + 32 * nw);
        if (!covered) {
            out[(2 * p) * RES + j]     = b[(2 * p) * RES + j];
            out[(2 * p + 1) * RES + j] = b[(2 * p + 1) * RES + j];
        }
    }

    // ---- flat balanced main loop (per-warp contiguous span of L items)
    const int K     = sK;
    const int WT    = sWT;
    const int total = WT * K;
    const int L     = (total + NWG - 1) / NWG;
    const int wg    = blockIdx.x * 32 + wid;
    int q0 = wg * (long long)L > total ? total : wg * L;
    int q1 = q0 + L; if (q1 > total) q1 = total;
    int rec = 0;

    while (q0 < q1) {
        const int t  = q0 / K;
        const int sa = q0 - t * K;
        int sb = sa + (q1 - q0); if (sb > K) sb = K;

        const int info = ttab[t];
        const int p  = info & 255;
        const int g  = (info >> 8) & 255;
        const int J0 = info >> 16;

        const float fi0 = (float)(2 * p);
        const float fj  = (float)(J0 + 32 * g + lane);   // may be >= 96 (discarded)
        const unsigned long long fi01 = pk2(fi0, fi0 + 1.0f);

        const float dic0 = fi0 - 48.0f;
        const float dic1 = dic0 + 1.0f;
        const float djc  = fj - 48.0f;
        const float z0 = 48.0f - sqrtf(dic0 * dic0 + djc * djc) + EPSF;
        const float z1 = 48.0f - sqrtf(dic1 * dic1 + djc * djc) + EPSF;
        const float c00 = fmaf(z0, z0, EPSF * EPSF);
        const float c01 = fmaf(z1, z1, EPSF * EPSF);

        float acc0 = 0.0f, acc1 = 0.0f;
        #pragma unroll 4
        for (int s = sa; s < sb; s++) {
            float4 e = ent[s];                           // broadcast LDS.128
            unsigned long long bi01 = pk2(e.x, e.y);
            unsigned long long di01;
            asm("add.rn.f32x2 %0, %1, %2;" : "=l"(di01) : "l"(fi01), "l"(bi01));
            float dj = fj - e.z;
            float u  = fmaf(dj, dj, c00);
            float v  = fmaf(dj, dj, c01);
            unsigned long long uv = pk2(u, v);
            unsigned long long den01;
            asm("fma.rn.f32x2 %0, %1, %2, %3;" : "=l"(den01)
                : "l"(di01), "l"(di01), "l"(uv));
            float den0, den1; unpk2(den01, den0, den1);
            float inv0, inv1;
            asm("rcp.approx.ftz.f32 %0, %1;" : "=f"(inv0) : "f"(den0));
            asm("rcp.approx.ftz.f32 %0, %1;" : "=f"(inv1) : "f"(den1));
            acc0 = fmaf(e.w, inv0, acc0);
            acc1 = fmaf(e.w, inv1, acc1);
        }

        const int slot = wid * 2 + rec;
        stile[slot] = t;
        spart[slot * 64 + lane]      = acc0;
        spart[slot * 64 + 32 + lane] = acc1;
        rec++;
        q0 = (sb < K) ? q1 : (t + 1) * K;                // advance past fragment
        if (sb < K) break;                                // span ended mid-tile
    }
    for (; rec < 2; rec++)
        if (lane == 0) stile[wid * 2 + rec] = -1;
    __syncthreads();

    // ---- intra-block reduction: 64 records -> <= (tB-tA+1) tile fragments
    if (total > 0) {
        const long long span = 32LL * L;
        const long long bq0  = (long long)blockIdx.x * span;
        if (bq0 < total) {
            long long bq1 = bq0 + span; if (bq1 > total) bq1 = total;
            const int tA = (int)(bq0 / K);
            const int tB = (int)((bq1 - 1) / K);
            const int c   = tid >> 6;    // 0..15
            const int pos = tid & 63;
            for (int t = tA; t <= tB; t++) {
                float s = 0.0f;
                #pragma unroll
                for (int r = 0; r < 4; r++) {
                    const int rc = c * 4 + r;
                    if (stile[rc] == t) s += spart[rc * 64 + pos];
                }
                red2[tid] = s;
                __syncthreads();
                if (tid < 64) {
                    float v = 0.0f;
                    #pragma unroll
                    for (int cc = 0; cc < 16; cc++) v += red2[cc * 64 + tid];
                    g_frag[((long long)blockIdx.x * MAXFRAG + (t - tA)) * 64 + tid] = v;
                }
                __syncthreads();
            }
        }
    }
}

// ==============================================================================
// Finish kernel: tile t sums its <= 3 block fragments (ascending block order,
// deterministic) and writes the 64 outputs with the exact integer rim select.
// ==============================================================================
__global__ void __launch_bounds__(64) finish_kernel(
    const float* __restrict__ b, float* __restrict__ out)
{
    __shared__ int tnw[48], tJ0[48], toff[48], ttab[144], sWT;
    const int tid = threadIdx.x;

    build_tiles(tid, tnw, tJ0, toff, ttab, &sWT);

    const int t  = blockIdx.x;
    const int WT = sWT;
    if (t >= WT) return;

    const int info = ttab[t];
    const int p  = info & 255;
    const int g  = (info >> 8) & 255;
    const int J0 = info >> 16;

    const int K = g_K;
    const int total = WT * K;
    float s = 0.0f;
    if (total > 0) {
        const int L = (total + NWG - 1) / NWG;
        const long long span = 32LL * L;
        const int blo = (int)(((long long)t * K) / span);
        const int bhi = (int)((((long long)(t + 1) * K) - 1) / span);
        #pragma unroll 1
        for (int blk = blo; blk <= bhi; blk++) {
            const int tA = (int)(((long long)blk * span) / K);
            s += g_frag[((long long)blk * MAXFRAG + (t - tA)) * 64 + tid];
        }
    }

    const int k  = tid >> 5;
    const int l  = tid & 31;
    const int ii = 2 * p + k;
    const int jj = J0 + 32 * g + l;
    if (jj < RES) {
        const int di = ii - 48, dj = jj - 48;
        const float bv = b[ii * RES + jj];
        out[ii * RES + jj] = (di * di + dj * dj >= 2209) ? bv : s;
    }
}

// ------------------------------------------------------------------------------
extern "C" void kernel_launch(void* const* d_in, const int* in_sizes, int n_in,
                              void* d_out, int out_size) {
    (void)in_sizes; (void)n_in; (void)out_size;
    const float* b   = (const float*)d_in[0];
    float*       out = (float*)d_out;

    const int smem_bytes = CAP * (int)sizeof(float4);    // 147456
    cudaFuncSetAttribute(main_kernel,
                         cudaFuncAttributeMaxDynamicSharedMemorySize, smem_bytes);

    main_kernel<<<MAIN_BLOCKS, 1024, smem_bytes>>>(b, out);
    finish_kernel<<<144, 64>>>(b, out);
}

// round 6
// speedup vs baseline: 1.3034x; 1.0869x over previous
#include <cuda_runtime.h>

#define RES         96
#define EPSF        1e-5f
#define CAP         (RES * RES)        // 9216 entries
#define MAIN_BLOCKS 148
#define NWG         (MAIN_BLOCKS * 32) // 4736 warps
#define MAXFRAG     34                 // worst-case tile fragments per block

// Global scratch (static — no cudaMalloc).
__device__ float            g_frag[MAIN_BLOCKS * MAXFRAG * 64];
__device__ unsigned int     g_arrive;   // monotone grid-barrier counter (replay-safe)

// ---- f32x2 helpers ----------------------------------------------------------
__device__ __forceinline__ unsigned long long pk2(float a, float b) {
    unsigned long long r;
    asm("mov.b64 %0, {%1, %2};" : "=l"(r) : "f"(a), "f"(b));
    return r;
}
__device__ __forceinline__ void unpk2(unsigned long long v, float& a, float& b) {
    asm("mov.b64 {%0, %1}, %2;" : "=f"(a), "=f"(b) : "l"(v));
}

// ---- deterministic tile geometry ---------------------------------------------
// i-pair p (rows 2p,2p+1): dmin = min row distance to center; interior
// half-width wI = floor(sqrt(2208 - dmin^2)); nw 32-wide windows from J0=47-wI.
__device__ __forceinline__ void build_tiles(int tid, int* tnw, int* tJ0,
                                             int* toff, int* ttab, int* pWT)
{
    if (tid < 48) {
        int p = tid;
        int d0 = 2 * p - 48;     if (d0 < 0) d0 = -d0;
        int d1 = 2 * p + 1 - 48; if (d1 < 0) d1 = -d1;
        int dmin = d0 < d1 ? d0 : d1;
        int v = 2208 - dmin * dmin;
        int nw = 0, J0 = 0;
        if (v >= 0) {
            int wI = (int)sqrtf((float)v);
            while ((wI + 1) * (wI + 1) <= v) wI++;   // exact isqrt
            while (wI * wI > v) wI--;
            J0 = 47 - wI;
            nw = (2 * wI + 2 + 31) >> 5;             // <= 3
        }
        tnw[p] = nw; tJ0[p] = J0;
    }
    __syncthreads();
    if (tid == 0) {
        int s = 0;
        #pragma unroll 1
        for (int p = 0; p < 48; p++) { toff[p] = s; s += tnw[p]; }
        *pWT = s;                                    // WT <= 144 (typ. 117)
    }
    __syncthreads();
    if (tid < 48) {
        int p = tid;
        for (int g = 0; g < tnw[p]; g++)
            ttab[toff[p] + g] = p | (g << 8) | (tJ0[p] << 16);
    }
    __syncthreads();
}

// ==============================================================================
// Single fused kernel: compaction + flat balanced evaluation + block reduction
// + grid barrier + final tile reduction.  148 blocks x 1024 threads, 1 block/SM
// -> all blocks resident, spin barrier deadlock-free.
// ==============================================================================
__global__ void __launch_bounds__(1024, 1) fused_kernel(
    const float* __restrict__ b, float* __restrict__ out)
{
    extern __shared__ float4 ent[];              // CAP * 16 B dynamic
    __shared__ int   cnts[RES], offs[RES], sK;
    __shared__ int   tnw[48], tJ0[48], toff[48], ttab[144], sWT;
    __shared__ float spart[64 * 64];             // 32 warps x 2 records x 64
    __shared__ int   stile[64];
    __shared__ float red2[1024];

    const int tid  = threadIdx.x;
    const int wid  = tid >> 5;
    const int lane = tid & 31;

    build_tiles(tid, tnw, tJ0, toff, ttab, &sWT);

    // ---- compaction: positive boundary -> (-bi, -bi, bj, w), row-major order
    {
        const int r0 = wid * 3;
        #pragma unroll
        for (int rr = 0; rr < 3; rr++) {
            const int row = r0 + rr;
            int c = 0;
            #pragma unroll
            for (int s = 0; s < 3; s++) {
                float v = b[row * RES + s * 32 + lane];
                c += __popc(__ballot_sync(0xffffffffu, v > 0.0f));
            }
            if (lane == 0) cnts[row] = c;
        }
    }
    __syncthreads();
    if (wid == 0) {                              // exclusive prefix of 96 counts
        int a0 = cnts[lane], a1 = cnts[lane + 32], a2 = cnts[lane + 64];
        int s0 = a0, s1 = a1, s2 = a2;
        #pragma unroll
        for (int d = 1; d < 32; d <<= 1) {
            int t0 = __shfl_up_sync(0xffffffffu, s0, d); if (lane >= d) s0 += t0;
            int t1 = __shfl_up_sync(0xffffffffu, s1, d); if (lane >= d) s1 += t1;
            int t2 = __shfl_up_sync(0xffffffffu, s2, d); if (lane >= d) s2 += t2;
        }
        s1 += __shfl_sync(0xffffffffu, s0, 31);
        s2 += __shfl_sync(0xffffffffu, s1, 31);
        offs[lane]      = s0 - a0;
        offs[lane + 32] = s1 - a1;
        offs[lane + 64] = s2 - a2;
        if (lane == 31) sK = s2;
    }
    __syncthreads();
    {
        const int r0 = wid * 3;
        #pragma unroll
        for (int rr = 0; rr < 3; rr++) {
            const int row = r0 + rr;
            int p = offs[row];
            #pragma unroll
            for (int s = 0; s < 3; s++) {
                const int col = s * 32 + lane;
                float v = b[row * RES + col];
                unsigned m = __ballot_sync(0xffffffffu, v > 0.0f);
                if (v > 0.0f) {
                    int pos = p + __popc(m & ((1u << lane) - 1u));
                    ent[pos] = make_float4(-(float)row, -(float)row, (float)col, v);
                }
                p += __popc(m);
            }
        }
    }
    __syncthreads();

    // ---- rim passthrough for uncovered columns (blocks 0..47)
    if (blockIdx.x < 48 && tid < RES) {
        const int p = blockIdx.x, j = tid;
        const int nw = tnw[p], J0 = tJ0[p];
        const bool covered = (nw > 0) && (j >= J0) && (j < J0 + 32 * nw);
        if (!covered) {
            out[(2 * p) * RES + j]     = b[(2 * p) * RES + j];
            out[(2 * p + 1) * RES + j] = b[(2 * p + 1) * RES + j];
        }
    }

    // ---- flat balanced main loop (per-warp contiguous span of L items)
    const int K     = sK;
    const int WT    = sWT;
    const int total = WT * K;
    const int L     = (total + NWG - 1) / NWG;
    const int wg    = blockIdx.x * 32 + wid;
    int q0 = (total > 0 && wg * L < total) ? wg * L : total;
    int q1 = q0 + L; if (q1 > total) q1 = total;
    int rec = 0;

    while (q0 < q1) {
        const int t  = q0 / K;
        const int sa = q0 - t * K;
        int sb = sa + (q1 - q0); if (sb > K) sb = K;

        const int info = ttab[t];
        const int p  = info & 255;
        const int g  = (info >> 8) & 255;
        const int J0 = info >> 16;

        const float fi0 = (float)(2 * p);
        const float fj  = (float)(J0 + 32 * g + lane);   // may be >= 96 (discarded)
        const unsigned long long fi01 = pk2(fi0, fi0 + 1.0f);

        const float dic0 = fi0 - 48.0f;
        const float dic1 = dic0 + 1.0f;
        const float djc  = fj - 48.0f;
        const float z0 = 48.0f - sqrtf(dic0 * dic0 + djc * djc) + EPSF;
        const float z1 = 48.0f - sqrtf(dic1 * dic1 + djc * djc) + EPSF;
        const float c00 = fmaf(z0, z0, EPSF * EPSF);
        const float c01 = fmaf(z1, z1, EPSF * EPSF);

        float acc0 = 0.0f, acc1 = 0.0f;
        #pragma unroll 4
        for (int s = sa; s < sb; s++) {
            float4 e = ent[s];                           // broadcast LDS.128
            unsigned long long bi01 = pk2(e.x, e.y);
            unsigned long long di01;
            asm("add.rn.f32x2 %0, %1, %2;" : "=l"(di01) : "l"(fi01), "l"(bi01));
            float dj = fj - e.z;
            float u  = fmaf(dj, dj, c00);
            float v  = fmaf(dj, dj, c01);
            unsigned long long uv = pk2(u, v);
            unsigned long long den01;
            asm("fma.rn.f32x2 %0, %1, %2, %3;" : "=l"(den01)
                : "l"(di01), "l"(di01), "l"(uv));
            float den0, den1; unpk2(den01, den0, den1);
            float inv0, inv1;
            asm("rcp.approx.ftz.f32 %0, %1;" : "=f"(inv0) : "f"(den0));
            asm("rcp.approx.ftz.f32 %0, %1;" : "=f"(inv1) : "f"(den1));
            acc0 = fmaf(e.w, inv0, acc0);
            acc1 = fmaf(e.w, inv1, acc1);
        }

        const int slot = wid * 2 + rec;
        stile[slot] = t;
        spart[slot * 64 + lane]      = acc0;
        spart[slot * 64 + 32 + lane] = acc1;
        rec++;
        if (sb < K) break;                               // span ended mid-tile
        q0 = (t + 1) * K;
    }
    for (; rec < 2; rec++)
        if (lane == 0) stile[wid * 2 + rec] = -1;
    __syncthreads();

    // ---- intra-block reduction: 64 records -> block tile fragments in global
    if (total > 0) {
        const long long span = 32LL * L;
        const long long bq0  = (long long)blockIdx.x * span;
        if (bq0 < total) {
            long long bq1 = bq0 + span; if (bq1 > total) bq1 = total;
            const int tA = (int)(bq0 / K);
            const int tB = (int)((bq1 - 1) / K);
            const int c   = tid >> 6;    // 0..15
            const int pos = tid & 63;
            for (int t = tA; t <= tB; t++) {
                float s = 0.0f;
                #pragma unroll
                for (int r = 0; r < 4; r++) {
                    const int rc = c * 4 + r;
                    if (stile[rc] == t) s += spart[rc * 64 + pos];
                }
                red2[tid] = s;
                __syncthreads();
                if (tid < 64) {
                    float v = 0.0f;
                    #pragma unroll
                    for (int cc = 0; cc < 16; cc++) v += red2[cc * 64 + tid];
                    g_frag[((long long)blockIdx.x * MAXFRAG + (t - tA)) * 64 + tid] = v;
                }
                __syncthreads();
            }
        }
    }

    // ---- grid-wide barrier (all 148 blocks resident; replay-safe ticketing)
    __syncthreads();
    if (tid == 0) {
        __threadfence();                                 // publish g_frag writes
        unsigned int my = atomicAdd(&g_arrive, 1u);
        const unsigned int goal = (my / MAIN_BLOCKS + 1u) * MAIN_BLOCKS;
        while (true) {
            unsigned int cur;
            asm volatile("ld.acquire.gpu.u32 %0, [%1];"
                         : "=r"(cur) : "l"(&g_arrive));
            if (cur >= goal) break;
            __nanosleep(64);
        }
    }
    __syncthreads();

    // ---- final tile reduction: block t sums its <= few fragments (ascending
    //      block order, deterministic) and writes 64 outputs.
    const int t = blockIdx.x;
    if (t < WT && tid < 64) {
        const int info = ttab[t];
        const int p  = info & 255;
        const int g  = (info >> 8) & 255;
        const int J0 = info >> 16;

        float s = 0.0f;
        if (total > 0) {
            const long long span = 32LL * L;
            const int blo = (int)(((long long)t * K) / span);
            const int bhi = (int)((((long long)(t + 1) * K) - 1) / span);
            #pragma unroll 1
            for (int blk = blo; blk <= bhi; blk++) {
                const int tA = (int)(((long long)blk * span) / K);
                s += __ldcg(&g_frag[((long long)blk * MAXFRAG + (t - tA)) * 64 + tid]);
            }
        }

        const int k  = tid >> 5;
        const int l  = tid & 31;
        const int ii = 2 * p + k;
        const int jj = J0 + 32 * g + l;
        if (jj < RES) {
            const int di = ii - 48, dj = jj - 48;
            const float bv = b[ii * RES + jj];
            out[ii * RES + jj] = (di * di + dj * dj >= 2209) ? bv : s;
        }
    }
}

// ------------------------------------------------------------------------------
extern "C" void kernel_launch(void* const* d_in, const int* in_sizes, int n_in,
                              void* d_out, int out_size) {
    (void)in_sizes; (void)n_in; (void)out_size;
    const float* b   = (const float*)d_in[0];
    float*       out = (float*)d_out;

    const int smem_bytes = CAP * (int)sizeof(float4);    // 147456
    cudaFuncSetAttribute(fused_kernel,
                         cudaFuncAttributeMaxDynamicSharedMemorySize, smem_bytes);

    fused_kernel<<<MAIN_BLOCKS, 1024, smem_bytes>>>(b, out);
}